// round 16
// baseline (speedup 1.0000x reference)
#include <cuda_runtime.h>
#include <cuda_fp16.h>
#include <math.h>
#include <limits.h>

#define Nn    20000
#define Ee    320000
#define ETOT  340000   // Ee + Nn self loops
#define DIN   128
#define HIDC  128
#define NH1   4
#define F1    512      // NH1*HIDC
#define DOUT  32
#define NTILES ((Nn + 255) / 256)   // 79

// ---------------- scratch (device globals; allocation-free) ----------------
__device__ __align__(16) float  g_h0  [Nn*DIN];
__device__ __align__(16) __half g_xh1 [(size_t)Nn*F1];
__device__ __align__(16) float  g_al1s[Nn*NH1];
__device__ __align__(16) float  g_al1d[Nn*NH1];
__device__ __align__(16) float  g_h1  [(size_t)Nn*F1];
__device__ __align__(16) __half g_xh2 [Nn*HIDC];
__device__              float   g_al2s[Nn];
__device__              float   g_al2d[Nn];
__device__              int     g_src [ETOT];
__device__              int     g_dst [ETOT];
__device__              int     g_deg [Nn];
__device__              int     g_scantmp[Nn];
__device__              int     g_tilesum[128];
__device__              int     g_tileoff[128];
__device__              int     g_rowptr[Nn+1];
__device__              int     g_cursor[Nn];
__device__              int     g_csr_src[ETOT];
__device__              int     g_is32;

// ---------------- helpers ----------------
__device__ __forceinline__ float wsum(float v){
    #pragma unroll
    for (int o = 16; o; o >>= 1) v += __shfl_xor_sync(0xffffffffu, v, o);
    return v;
}
__device__ __forceinline__ float wmax(float v){
    #pragma unroll
    for (int o = 16; o; o >>= 1) v = fmaxf(v, __shfl_xor_sync(0xffffffffu, v, o));
    return v;
}
__device__ __forceinline__ float gelu_exact(float x){
    return 0.5f * x * (1.0f + erff(x * 0.70710678118654752f));
}
__device__ __forceinline__ unsigned tf32_of(float x){
    unsigned u; asm("cvt.rna.tf32.f32 %0, %1;" : "=r"(u) : "f"(x)); return u;
}
__device__ __forceinline__ float lrelu(float x){ return x > 0.f ? x : 0.2f * x; }

__device__ __forceinline__ float4 h4_to_f4(unsigned lo, unsigned hi){
    __half2 l = *reinterpret_cast<__half2*>(&lo);
    __half2 h = *reinterpret_cast<__half2*>(&hi);
    float2 a = __half22float2(l), b = __half22float2(h);
    return make_float4(a.x, a.y, b.x, b.y);
}

// ---------------- edge dtype detection + decode (+degree count) ----------------
__global__ void detect_dtype(const long long* __restrict__ p){
    long long stride = (2LL * Ee) / 4096;
    if (stride < 1) stride = 1;
    long long idx = (long long)(blockIdx.x * blockDim.x + threadIdx.x) * stride;
    if (idx >= 2LL * Ee) return;
    long long v = p[idx];
    if (v < 0 || v >= Nn) atomicExch(&g_is32, 1);
}

__global__ void decode_edges(const int* __restrict__ p32){
    int e = blockIdx.x * blockDim.x + threadIdx.x;
    if (e >= ETOT) return;
    int s, d;
    if (e < Ee){
        if (g_is32){ s = p32[e];   d = p32[Ee + e]; }
        else       { s = p32[2*e]; d = p32[2*Ee + 2*e]; }
    } else {
        s = d = e - Ee;
    }
    g_src[e] = s; g_dst[e] = d;
    atomicAdd(&g_deg[d], 1);
}

// ---------------- parallel 3-kernel scan of g_deg -> g_rowptr ----------------
__global__ void scan_tiles(){
    __shared__ int sh[256];
    int i = blockIdx.x * 256 + threadIdx.x;
    int v = (i < Nn) ? g_deg[i] : 0;
    sh[threadIdx.x] = v;
    __syncthreads();
    for (int off = 1; off < 256; off <<= 1){
        int t = (threadIdx.x >= off) ? sh[threadIdx.x - off] : 0;
        __syncthreads();
        sh[threadIdx.x] += t;
        __syncthreads();
    }
    if (i < Nn) g_scantmp[i] = sh[threadIdx.x];
    if (threadIdx.x == 255) g_tilesum[blockIdx.x] = sh[255];
}

__global__ void scan_sums(){
    __shared__ int sh[128];
    int t = threadIdx.x;
    sh[t] = (t < NTILES) ? g_tilesum[t] : 0;
    __syncthreads();
    for (int off = 1; off < 128; off <<= 1){
        int v = (t >= off) ? sh[t - off] : 0;
        __syncthreads();
        sh[t] += v;
        __syncthreads();
    }
    if (t < NTILES) g_tileoff[t] = (t == 0) ? 0 : sh[t - 1];
}

__global__ void scan_finalize(){
    int i = blockIdx.x * 256 + threadIdx.x;
    if (i >= Nn) return;
    int r = g_scantmp[i] - g_deg[i] + g_tileoff[i >> 8];
    g_rowptr[i] = r;
    g_cursor[i] = r;
    if (i == 0) g_rowptr[Nn] = ETOT;
}

__global__ void build_csr(){
    int e = blockIdx.x * blockDim.x + threadIdx.x;
    if (e >= ETOT) return;
    int pos = atomicAdd(&g_cursor[g_dst[e]], 1);
    g_csr_src[pos] = g_src[e];
}

// ---------------- standalone LayerNorm (input only) ----------------
template<int D>
__global__ void ln_kernel(const float* __restrict__ in, const float* __restrict__ g,
                          const float* __restrict__ b, float* __restrict__ out){
    int row = blockIdx.x * (blockDim.x >> 5) + (threadIdx.x >> 5);
    if (row >= Nn) return;
    int lane = threadIdx.x & 31;
    constexpr int V = D / 128;
    float4 v[V];
    const float4* ir = (const float4*)(in + (size_t)row * D);
    float s = 0.f;
    #pragma unroll
    for (int i = 0; i < V; i++){
        v[i] = ir[lane + i*32];
        s += v[i].x + v[i].y + v[i].z + v[i].w;
    }
    s = wsum(s);
    float mu = s * (1.0f / D);
    float q = 0.f;
    #pragma unroll
    for (int i = 0; i < V; i++){
        float dx;
        dx = v[i].x - mu; q += dx*dx;
        dx = v[i].y - mu; q += dx*dx;
        dx = v[i].z - mu; q += dx*dx;
        dx = v[i].w - mu; q += dx*dx;
    }
    q = wsum(q);
    float rstd = rsqrtf(q * (1.0f / D) + 1e-5f);
    float4* orow = (float4*)(out + (size_t)row * D);
    #pragma unroll
    for (int i = 0; i < V; i++){
        float4 gg = ((const float4*)g)[lane + i*32];
        float4 bb = ((const float4*)b)[lane + i*32];
        float4 y;
        y.x = (v[i].x - mu) * rstd * gg.x + bb.x;
        y.y = (v[i].y - mu) * rstd * gg.y + bb.y;
        y.z = (v[i].z - mu) * rstd * gg.z + bb.z;
        y.w = (v[i].w - mu) * rstd * gg.w + bb.w;
        orow[lane + i*32] = y;
    }
}

// ---------------- tf32 tensor-core GEMM: C[n,m](fp16) = A[n,k] @ B[k,m] ----------------
#define GBM 128
#define GBN 64
#define GBK 32
#define AS_STRIDE (GBK + 4)
#define BS_STRIDE (GBN + 4)

__global__ void __launch_bounds__(256, 2) gemm_tf32(const float* __restrict__ A,
                                                    const float* __restrict__ B,
                                                    __half* __restrict__ C,
                                                    int n, int k, int m){
    __shared__ float As[GBM][AS_STRIDE];
    __shared__ float Bs[GBK][BS_STRIDE];

    int tid  = threadIdx.x;
    int wid  = tid >> 5;
    int lane = tid & 31;
    int wm   = (wid & 3) * 32;
    int wn   = (wid >> 2) * 32;
    int grp  = lane >> 2;
    int tg   = lane & 3;

    int bm = blockIdx.y * GBM;
    int bn = blockIdx.x * GBN;

    float acc[2][4][4];
    #pragma unroll
    for (int i=0;i<2;i++)
        #pragma unroll
        for (int j=0;j<4;j++)
            #pragma unroll
            for (int l=0;l<4;l++) acc[i][j][l] = 0.f;

    int arow  = tid >> 3;
    int acol  = (tid & 7) * 4;
    int brow  = tid >> 4;
    int bcol  = (tid & 15) * 4;

    for (int k0 = 0; k0 < k; k0 += GBK){
        #pragma unroll
        for (int i = 0; i < 4; i++){
            int row = arow + i*32;
            float4 v = make_float4(0,0,0,0);
            int gr = bm + row;
            if (gr < n) v = *(const float4*)&A[(size_t)gr * k + k0 + acol];
            As[row][acol+0] = __uint_as_float(tf32_of(v.x));
            As[row][acol+1] = __uint_as_float(tf32_of(v.y));
            As[row][acol+2] = __uint_as_float(tf32_of(v.z));
            As[row][acol+3] = __uint_as_float(tf32_of(v.w));
        }
        #pragma unroll
        for (int i = 0; i < 2; i++){
            int row = brow + i*16;
            float4 v = *(const float4*)&B[(size_t)(k0 + row) * m + bn + bcol];
            Bs[row][bcol+0] = __uint_as_float(tf32_of(v.x));
            Bs[row][bcol+1] = __uint_as_float(tf32_of(v.y));
            Bs[row][bcol+2] = __uint_as_float(tf32_of(v.z));
            Bs[row][bcol+3] = __uint_as_float(tf32_of(v.w));
        }
        __syncthreads();

        #pragma unroll
        for (int kk = 0; kk < 4; kk++){
            unsigned a[2][4], bfr[4][2];
            #pragma unroll
            for (int mt = 0; mt < 2; mt++){
                int r = wm + mt*16 + grp;
                int c = kk*8 + tg;
                a[mt][0] = __float_as_uint(As[r    ][c    ]);
                a[mt][1] = __float_as_uint(As[r + 8][c    ]);
                a[mt][2] = __float_as_uint(As[r    ][c + 4]);
                a[mt][3] = __float_as_uint(As[r + 8][c + 4]);
            }
            #pragma unroll
            for (int nt = 0; nt < 4; nt++){
                int c = wn + nt*8 + grp;
                int r = kk*8 + tg;
                bfr[nt][0] = __float_as_uint(Bs[r    ][c]);
                bfr[nt][1] = __float_as_uint(Bs[r + 4][c]);
            }
            #pragma unroll
            for (int mt = 0; mt < 2; mt++)
                #pragma unroll
                for (int nt = 0; nt < 4; nt++){
                    asm volatile(
                        "mma.sync.aligned.m16n8k8.row.col.f32.tf32.tf32.f32 "
                        "{%0,%1,%2,%3}, {%4,%5,%6,%7}, {%8,%9}, {%0,%1,%2,%3};"
                        : "+f"(acc[mt][nt][0]), "+f"(acc[mt][nt][1]),
                          "+f"(acc[mt][nt][2]), "+f"(acc[mt][nt][3])
                        : "r"(a[mt][0]), "r"(a[mt][1]), "r"(a[mt][2]), "r"(a[mt][3]),
                          "r"(bfr[nt][0]), "r"(bfr[nt][1]));
                }
        }
        __syncthreads();
    }

    #pragma unroll
    for (int mt = 0; mt < 2; mt++){
        int r0 = bm + wm + mt*16 + grp;
        int r1 = r0 + 8;
        #pragma unroll
        for (int nt = 0; nt < 4; nt++){
            int c = bn + wn + nt*8 + 2*tg;
            if (r0 < n) *(__half2*)&C[(size_t)r0 * m + c] = __floats2half2_rn(acc[mt][nt][0], acc[mt][nt][1]);
            if (r1 < n) *(__half2*)&C[(size_t)r1 * m + c] = __floats2half2_rn(acc[mt][nt][2], acc[mt][nt][3]);
        }
    }
}

// ------- attention logits H=4: ONE warp per node; 2x uint4 per lane = full 512 halves -------
__global__ void attn_logits4(const __half* __restrict__ xh, const float* __restrict__ as_,
                             const float* __restrict__ ad_, float* __restrict__ als,
                             float* __restrict__ ald){
    int node = (blockIdx.x * blockDim.x + threadIdx.x) >> 5;
    if (node >= Nn) return;
    int lane = threadIdx.x & 31;
    int hd = lane >> 3;
    int sl = lane & 7;

    const uint4* xr = (const uint4*)(xh + (size_t)node * F1) + hd*16 + sl*2;
    uint4 u0 = xr[0], u1 = xr[1];
    float4 x0 = h4_to_f4(u0.x, u0.y);
    float4 x1 = h4_to_f4(u0.z, u0.w);
    float4 x2 = h4_to_f4(u1.x, u1.y);
    float4 x3 = h4_to_f4(u1.z, u1.w);
    const float4* svp = (const float4*)(as_ + hd * HIDC) + sl*4;
    const float4* dvp = (const float4*)(ad_ + hd * HIDC) + sl*4;
    float4 s0 = svp[0], s1 = svp[1], s2 = svp[2], s3 = svp[3];
    float4 d0 = dvp[0], d1 = dvp[1], d2 = dvp[2], d3 = dvp[3];
    float s = x0.x*s0.x + x0.y*s0.y + x0.z*s0.z + x0.w*s0.w
            + x1.x*s1.x + x1.y*s1.y + x1.z*s1.z + x1.w*s1.w
            + x2.x*s2.x + x2.y*s2.y + x2.z*s2.z + x2.w*s2.w
            + x3.x*s3.x + x3.y*s3.y + x3.z*s3.z + x3.w*s3.w;
    float d = x0.x*d0.x + x0.y*d0.y + x0.z*d0.z + x0.w*d0.w
            + x1.x*d1.x + x1.y*d1.y + x1.z*d1.z + x1.w*d1.w
            + x2.x*d2.x + x2.y*d2.y + x2.z*d2.z + x2.w*d2.w
            + x3.x*d3.x + x3.y*d3.y + x3.z*d3.z + x3.w*d3.w;
    #pragma unroll
    for (int o = 4; o; o >>= 1){
        s += __shfl_xor_sync(0xffffffffu, s, o);
        d += __shfl_xor_sync(0xffffffffu, d, o);
    }
    if (sl == 0){ als[node*NH1 + hd] = s; ald[node*NH1 + hd] = d; }
}

// ------- attention logits H=1 (fp16 features) -------
__global__ void attn_logits1(const __half* __restrict__ xh, const float* __restrict__ as_,
                             const float* __restrict__ ad_, float* __restrict__ als,
                             float* __restrict__ ald){
    int w = (blockIdx.x * blockDim.x + threadIdx.x) >> 5;
    if (w >= Nn) return;
    int lane = threadIdx.x & 31;
    uint2 u = ((const uint2*)(xh + (size_t)w * HIDC))[lane];
    float4 x = h4_to_f4(u.x, u.y);
    float4 sv = ((const float4*)as_)[lane];
    float4 dv = ((const float4*)ad_)[lane];
    float s = x.x*sv.x + x.y*sv.y + x.z*sv.z + x.w*sv.w;
    float d = x.x*dv.x + x.y*dv.y + x.z*dv.z + x.w*dv.w;
    s = wsum(s); d = wsum(d);
    if (lane == 0){ als[w] = s; ald[w] = d; }
}

// ------ GAT agg H=4: two warps/node; SINGLE PASS (no max shift — logits << 88) ------
__global__ void __launch_bounds__(256) gat_agg4_fused(const float4* __restrict__ als4,
                                                      const float4* __restrict__ ald4,
                                                      const __half* __restrict__ xh,
                                                      const float* __restrict__ bias,
                                                      const float* __restrict__ gw,
                                                      const float* __restrict__ bw,
                                                      float* __restrict__ h1){
    __shared__ float s_part[8], q_part[8];
    int wib  = threadIdx.x >> 5;
    int node = blockIdx.x * 4 + (wib >> 1);
    int sub  = wib & 1;
    int lane = threadIdx.x & 31;
    int hsel = lane >> 4;

    float4 adv = ald4[node];
    float ad0 = sub ? adv.z : adv.x;
    float ad1 = sub ? adv.w : adv.y;
    int pbeg = g_rowptr[node], pend = g_rowptr[node+1];

    // single pass: e = exp(lrelu(logit)), den accumulated identically per lane
    float den0 = 0.f, den1 = 0.f;
    float4 aA = make_float4(0,0,0,0), aB = aA;
    #pragma unroll 4
    for (int p = pbeg; p < pend; p++){
        int s = g_csr_src[p];
        float4 as = als4[s];
        float e0 = __expf(lrelu((sub ? as.z : as.x) + ad0));
        float e1 = __expf(lrelu((sub ? as.w : as.y) + ad1));
        den0 += e0; den1 += e1;
        float e = hsel ? e1 : e0;
        uint4 u = ((const uint4*)(xh + (size_t)s * F1 + sub*256))[lane];
        float4 xA = h4_to_f4(u.x, u.y);
        float4 xB = h4_to_f4(u.z, u.w);
        aA.x += e*xA.x; aA.y += e*xA.y; aA.z += e*xA.z; aA.w += e*xA.w;
        aB.x += e*xB.x; aB.y += e*xB.y; aB.z += e*xB.z; aB.w += e*xB.w;
    }
    float rh = 1.f / (hsel ? den1 : den0);

    // epilogue: bias; LN over 512 (warp + pair reduce); gelu; write
    const float4* b4 = (const float4*)bias + sub*64 + lane*2;
    float4 qA = b4[0], qB = b4[1];
    float4 vA, vB;
    vA.x = aA.x*rh + qA.x; vA.y = aA.y*rh + qA.y; vA.z = aA.z*rh + qA.z; vA.w = aA.w*rh + qA.w;
    vB.x = aB.x*rh + qB.x; vB.y = aB.y*rh + qB.y; vB.z = aB.z*rh + qB.z; vB.w = aB.w*rh + qB.w;

    float ssum = wsum(vA.x+vA.y+vA.z+vA.w + vB.x+vB.y+vB.z+vB.w);
    if (lane == 0) s_part[wib] = ssum;
    __syncthreads();
    int base = wib & ~1;
    float mu = (s_part[base] + s_part[base+1]) * (1.0f / F1);

    float q = 0.f, dx;
    dx=vA.x-mu; q+=dx*dx; dx=vA.y-mu; q+=dx*dx; dx=vA.z-mu; q+=dx*dx; dx=vA.w-mu; q+=dx*dx;
    dx=vB.x-mu; q+=dx*dx; dx=vB.y-mu; q+=dx*dx; dx=vB.z-mu; q+=dx*dx; dx=vB.w-mu; q+=dx*dx;
    q = wsum(q);
    if (lane == 0) q_part[wib] = q;
    __syncthreads();
    float rstd = rsqrtf((q_part[base] + q_part[base+1]) * (1.0f / F1) + 1e-5f);

    const float4* g4 = (const float4*)gw + sub*64 + lane*2;
    const float4* w4 = (const float4*)bw + sub*64 + lane*2;
    float4* orow = (float4*)(h1 + (size_t)node * F1) + sub*64 + lane*2;
    float4 gg = g4[0], bb = w4[0];
    float4 y;
    y.x = gelu_exact((vA.x - mu) * rstd * gg.x + bb.x);
    y.y = gelu_exact((vA.y - mu) * rstd * gg.y + bb.y);
    y.z = gelu_exact((vA.z - mu) * rstd * gg.z + bb.z);
    y.w = gelu_exact((vA.w - mu) * rstd * gg.w + bb.w);
    orow[0] = y;
    gg = g4[1]; bb = w4[1];
    y.x = gelu_exact((vB.x - mu) * rstd * gg.x + bb.x);
    y.y = gelu_exact((vB.y - mu) * rstd * gg.y + bb.y);
    y.z = gelu_exact((vB.z - mu) * rstd * gg.z + bb.z);
    y.w = gelu_exact((vB.w - mu) * rstd * gg.w + bb.w);
    orow[1] = y;
}

// ------- GAT agg H=1: SINGLE PASS + bias+LN+GELU+out_proj+log_softmax -------
__global__ void __launch_bounds__(256) gat_agg1_fused(const float* __restrict__ als,
                                                      const float* __restrict__ ald,
                                                      const __half* __restrict__ xh,
                                                      const float* __restrict__ bias,
                                                      const float* __restrict__ gw,
                                                      const float* __restrict__ bw,
                                                      const float* __restrict__ Wo,
                                                      const float* __restrict__ bo,
                                                      float* __restrict__ out){
    int node = blockIdx.x * (blockDim.x >> 5) + (threadIdx.x >> 5);
    if (node >= Nn) return;
    int lane = threadIdx.x & 31;
    float ad = ald[node];
    int pbeg = g_rowptr[node], pend = g_rowptr[node+1];

    float den = 0.f;
    float4 acc = make_float4(0,0,0,0);
    #pragma unroll 4
    for (int p = pbeg; p < pend; p++){
        int s = g_csr_src[p];
        float e = __expf(lrelu(als[s] + ad));
        den += e;
        uint2 u = ((const uint2*)(xh + (size_t)s * HIDC))[lane];
        float4 xv = h4_to_f4(u.x, u.y);
        acc.x += e*xv.x; acc.y += e*xv.y; acc.z += e*xv.z; acc.w += e*xv.w;
    }
    float r = 1.f/den;

    float4 qb = ((const float4*)bias)[lane];
    float4 v;
    v.x = acc.x*r + qb.x; v.y = acc.y*r + qb.y; v.z = acc.z*r + qb.z; v.w = acc.w*r + qb.w;
    float s = wsum(v.x + v.y + v.z + v.w);
    float mu = s * (1.0f / HIDC);
    float q = 0.f, dx;
    dx=v.x-mu; q+=dx*dx; dx=v.y-mu; q+=dx*dx; dx=v.z-mu; q+=dx*dx; dx=v.w-mu; q+=dx*dx;
    q = wsum(q);
    float rstd = rsqrtf(q * (1.0f / HIDC) + 1e-5f);
    float4 gg = ((const float4*)gw)[lane];
    float4 bb = ((const float4*)bw)[lane];
    float4 y;
    y.x = gelu_exact((v.x - mu) * rstd * gg.x + bb.x);
    y.y = gelu_exact((v.y - mu) * rstd * gg.y + bb.y);
    y.z = gelu_exact((v.z - mu) * rstd * gg.z + bb.z);
    y.w = gelu_exact((v.w - mu) * rstd * gg.w + bb.w);

    // fused output projection
    float z = bo[lane];
    #pragma unroll 8
    for (int k4 = 0; k4 < 32; k4++){
        float yx = __shfl_sync(0xffffffffu, y.x, k4);
        float yy = __shfl_sync(0xffffffffu, y.y, k4);
        float yz = __shfl_sync(0xffffffffu, y.z, k4);
        float yw = __shfl_sync(0xffffffffu, y.w, k4);
        const float* wr = Wo + k4*4*DOUT + lane;
        z += yx*wr[0] + yy*wr[DOUT] + yz*wr[2*DOUT] + yw*wr[3*DOUT];
    }
    float mx = wmax(z);
    float ex = expf(z - mx);
    float sm = wsum(ex);
    out[(size_t)node * DOUT + lane] = z - mx - logf(sm);
}

// ---------------- launch ----------------
extern "C" void kernel_launch(void* const* d_in, const int* in_sizes, int n_in,
                              void* d_out, int out_size){
    const float* x      = (const float*)d_in[0];
    const void*  ei     = d_in[1];
    const float* g_in   = (const float*)d_in[2];
    const float* b_in   = (const float*)d_in[3];
    const float* W1     = (const float*)d_in[4];
    const float* att1_s = (const float*)d_in[5];
    const float* att1_d = (const float*)d_in[6];
    const float* bias1  = (const float*)d_in[7];
    const float* g1     = (const float*)d_in[8];
    const float* b1     = (const float*)d_in[9];
    const float* W2     = (const float*)d_in[10];
    const float* att2_s = (const float*)d_in[11];
    const float* att2_d = (const float*)d_in[12];
    const float* bias2  = (const float*)d_in[13];
    const float* g2     = (const float*)d_in[14];
    const float* b2     = (const float*)d_in[15];
    const float* Wo     = (const float*)d_in[16];
    const float* bo     = (const float*)d_in[17];
    float* out = (float*)d_out;

    void *p_h0, *p_xh1, *p_al1s, *p_al1d, *p_h1;
    void *p_xh2, *p_al2s, *p_al2d, *p_is32, *p_deg;
    cudaGetSymbolAddress(&p_h0,   g_h0);
    cudaGetSymbolAddress(&p_xh1,  g_xh1);
    cudaGetSymbolAddress(&p_al1s, g_al1s);
    cudaGetSymbolAddress(&p_al1d, g_al1d);
    cudaGetSymbolAddress(&p_h1,   g_h1);
    cudaGetSymbolAddress(&p_xh2,  g_xh2);
    cudaGetSymbolAddress(&p_al2s, g_al2s);
    cudaGetSymbolAddress(&p_al2d, g_al2d);
    cudaGetSymbolAddress(&p_is32, g_is32);
    cudaGetSymbolAddress(&p_deg,  g_deg);

    const int T = 256;
    const int warpsPB = T / 32;

    // ---- side stream for CSR build (fork/join via events; capture-legal) ----
    cudaStream_t s2;
    cudaStreamCreate(&s2);
    cudaEvent_t evF, evJ;
    cudaEventCreateWithFlags(&evF, cudaEventDisableTiming);
    cudaEventCreateWithFlags(&evJ, cudaEventDisableTiming);

    cudaEventRecord(evF, 0);
    cudaStreamWaitEvent(s2, evF, 0);

    cudaMemsetAsync(p_is32, 0, sizeof(int), s2);
    cudaMemsetAsync(p_deg,  0, Nn * sizeof(int), s2);
    detect_dtype<<<16, 256, 0, s2>>>((const long long*)ei);
    decode_edges<<<(ETOT + T - 1)/T, T, 0, s2>>>((const int*)ei);
    scan_tiles<<<NTILES, 256, 0, s2>>>();
    scan_sums<<<1, 128, 0, s2>>>();
    scan_finalize<<<NTILES, 256, 0, s2>>>();
    build_csr<<<(ETOT + T - 1)/T, T, 0, s2>>>();
    cudaEventRecord(evJ, s2);

    // ---- dense path on main stream ----
    ln_kernel<128><<<(Nn + warpsPB - 1)/warpsPB, T>>>(x, g_in, b_in, (float*)p_h0);
    {
        dim3 grid(F1/GBN, (Nn + GBM - 1)/GBM);
        gemm_tf32<<<grid, 256>>>((const float*)p_h0, W1, (__half*)p_xh1, Nn, DIN, F1);
    }
    attn_logits4<<<(Nn + warpsPB - 1)/warpsPB, T>>>((const __half*)p_xh1, att1_s, att1_d,
                                                    (float*)p_al1s, (float*)p_al1d);

    // join CSR before aggregation
    cudaStreamWaitEvent(0, evJ, 0);

    gat_agg4_fused<<<Nn/4, T>>>((const float4*)p_al1s, (const float4*)p_al1d,
                                (const __half*)p_xh1, bias1, g1, b1, (float*)p_h1);

    {
        dim3 grid(HIDC/GBN, (Nn + GBM - 1)/GBM);
        gemm_tf32<<<grid, 256>>>((const float*)p_h1, W2, (__half*)p_xh2, Nn, F1, HIDC);
    }
    attn_logits1<<<(Nn + warpsPB - 1)/warpsPB, T>>>((const __half*)p_xh2, att2_s, att2_d,
                                                    (float*)p_al2s, (float*)p_al2d);
    gat_agg1_fused<<<(Nn + warpsPB - 1)/warpsPB, T>>>((const float*)p_al2s, (const float*)p_al2d,
                                                      (const __half*)p_xh2, bias2, g2, b2,
                                                      Wo, bo, out);
}

// round 17
// speedup vs baseline: 1.0534x; 1.0534x over previous
#include <cuda_runtime.h>
#include <cuda_fp16.h>
#include <math.h>
#include <limits.h>

#define Nn    20000
#define Ee    320000
#define ETOT  340000   // Ee + Nn self loops
#define DIN   128
#define HIDC  128
#define NH1   4
#define F1    512      // NH1*HIDC
#define DOUT  32
#define NTILES ((Nn + 255) / 256)   // 79

// ---------------- scratch (device globals; allocation-free) ----------------
__device__ __align__(16) float  g_h0  [Nn*DIN];
__device__ __align__(16) __half g_xh1 [(size_t)Nn*F1];
__device__ __align__(16) float  g_al1s[Nn*NH1];
__device__ __align__(16) float  g_al1d[Nn*NH1];
__device__ __align__(16) float  g_h1  [(size_t)Nn*F1];
__device__ __align__(16) __half g_xh2 [Nn*HIDC];
__device__              float   g_al2s[Nn];
__device__              float   g_al2d[Nn];
__device__              int     g_src [ETOT];
__device__              int     g_dst [ETOT];
__device__              int     g_deg [Nn];
__device__              int     g_scantmp[Nn];
__device__              int     g_tilesum[128];
__device__              int     g_tileoff[128];
__device__              int     g_rowptr[Nn+1];
__device__              int     g_cursor[Nn];
__device__              int     g_csr_src[ETOT];
__device__              int     g_is32;

// ---------------- helpers ----------------
__device__ __forceinline__ float wsum(float v){
    #pragma unroll
    for (int o = 16; o; o >>= 1) v += __shfl_xor_sync(0xffffffffu, v, o);
    return v;
}
__device__ __forceinline__ float wmax(float v){
    #pragma unroll
    for (int o = 16; o; o >>= 1) v = fmaxf(v, __shfl_xor_sync(0xffffffffu, v, o));
    return v;
}
__device__ __forceinline__ float gelu_exact(float x){
    return 0.5f * x * (1.0f + erff(x * 0.70710678118654752f));
}
__device__ __forceinline__ float lrelu(float x){ return x > 0.f ? x : 0.2f * x; }

__device__ __forceinline__ float4 h4_to_f4(unsigned lo, unsigned hi){
    __half2 l = *reinterpret_cast<__half2*>(&lo);
    __half2 h = *reinterpret_cast<__half2*>(&hi);
    float2 a = __half22float2(l), b = __half22float2(h);
    return make_float4(a.x, a.y, b.x, b.y);
}

__device__ __forceinline__ void cp16(void* dst_smem, const void* src, bool pred){
    unsigned saddr = (unsigned)__cvta_generic_to_shared(dst_smem);
    int sz = pred ? 16 : 0;
    asm volatile("cp.async.ca.shared.global [%0], [%1], 16, %2;"
                 :: "r"(saddr), "l"(src), "r"(sz));
}

// ---------------- edge dtype detection + decode (+degree count) ----------------
__global__ void detect_dtype(const long long* __restrict__ p){
    long long stride = (2LL * Ee) / 4096;
    if (stride < 1) stride = 1;
    long long idx = (long long)(blockIdx.x * blockDim.x + threadIdx.x) * stride;
    if (idx >= 2LL * Ee) return;
    long long v = p[idx];
    if (v < 0 || v >= Nn) atomicExch(&g_is32, 1);
}

__global__ void decode_edges(const int* __restrict__ p32){
    int e = blockIdx.x * blockDim.x + threadIdx.x;
    if (e >= ETOT) return;
    int s, d;
    if (e < Ee){
        if (g_is32){ s = p32[e];   d = p32[Ee + e]; }
        else       { s = p32[2*e]; d = p32[2*Ee + 2*e]; }
    } else {
        s = d = e - Ee;
    }
    g_src[e] = s; g_dst[e] = d;
    atomicAdd(&g_deg[d], 1);
}

// ---------------- parallel 3-kernel scan of g_deg -> g_rowptr ----------------
__global__ void scan_tiles(){
    __shared__ int sh[256];
    int i = blockIdx.x * 256 + threadIdx.x;
    int v = (i < Nn) ? g_deg[i] : 0;
    sh[threadIdx.x] = v;
    __syncthreads();
    for (int off = 1; off < 256; off <<= 1){
        int t = (threadIdx.x >= off) ? sh[threadIdx.x - off] : 0;
        __syncthreads();
        sh[threadIdx.x] += t;
        __syncthreads();
    }
    if (i < Nn) g_scantmp[i] = sh[threadIdx.x];
    if (threadIdx.x == 255) g_tilesum[blockIdx.x] = sh[255];
}

__global__ void scan_sums(){
    __shared__ int sh[128];
    int t = threadIdx.x;
    sh[t] = (t < NTILES) ? g_tilesum[t] : 0;
    __syncthreads();
    for (int off = 1; off < 128; off <<= 1){
        int v = (t >= off) ? sh[t - off] : 0;
        __syncthreads();
        sh[t] += v;
        __syncthreads();
    }
    if (t < NTILES) g_tileoff[t] = (t == 0) ? 0 : sh[t - 1];
}

__global__ void scan_finalize(){
    int i = blockIdx.x * 256 + threadIdx.x;
    if (i >= Nn) return;
    int r = g_scantmp[i] - g_deg[i] + g_tileoff[i >> 8];
    g_rowptr[i] = r;
    g_cursor[i] = r;
    if (i == 0) g_rowptr[Nn] = ETOT;
}

__global__ void build_csr(){
    int e = blockIdx.x * blockDim.x + threadIdx.x;
    if (e >= ETOT) return;
    int pos = atomicAdd(&g_cursor[g_dst[e]], 1);
    g_csr_src[pos] = g_src[e];
}

// ---------------- standalone LayerNorm (input only) ----------------
template<int D>
__global__ void ln_kernel(const float* __restrict__ in, const float* __restrict__ g,
                          const float* __restrict__ b, float* __restrict__ out){
    int row = blockIdx.x * (blockDim.x >> 5) + (threadIdx.x >> 5);
    if (row >= Nn) return;
    int lane = threadIdx.x & 31;
    constexpr int V = D / 128;
    float4 v[V];
    const float4* ir = (const float4*)(in + (size_t)row * D);
    float s = 0.f;
    #pragma unroll
    for (int i = 0; i < V; i++){
        v[i] = ir[lane + i*32];
        s += v[i].x + v[i].y + v[i].z + v[i].w;
    }
    s = wsum(s);
    float mu = s * (1.0f / D);
    float q = 0.f;
    #pragma unroll
    for (int i = 0; i < V; i++){
        float dx;
        dx = v[i].x - mu; q += dx*dx;
        dx = v[i].y - mu; q += dx*dx;
        dx = v[i].z - mu; q += dx*dx;
        dx = v[i].w - mu; q += dx*dx;
    }
    q = wsum(q);
    float rstd = rsqrtf(q * (1.0f / D) + 1e-5f);
    float4* orow = (float4*)(out + (size_t)row * D);
    #pragma unroll
    for (int i = 0; i < V; i++){
        float4 gg = ((const float4*)g)[lane + i*32];
        float4 bb = ((const float4*)b)[lane + i*32];
        float4 y;
        y.x = (v[i].x - mu) * rstd * gg.x + bb.x;
        y.y = (v[i].y - mu) * rstd * gg.y + bb.y;
        y.z = (v[i].z - mu) * rstd * gg.z + bb.z;
        y.w = (v[i].w - mu) * rstd * gg.w + bb.w;
        orow[lane + i*32] = y;
    }
}

// ---- tf32 GEMM, cp.async double-buffered 2-stage pipeline, fp16 output ----
#define GBM 128
#define GBN 64
#define GBK 32
#define AS_STRIDE (GBK + 4)    // 36 floats -> 144B row stride (16B aligned)
#define BS_STRIDE (GBN + 4)    // 68 floats -> 272B row stride (16B aligned)
#define GEMM_SMEM ((2*GBM*AS_STRIDE + 2*GBK*BS_STRIDE) * 4)   // 54272 B

__global__ void __launch_bounds__(256, 2) gemm_tf32(const float* __restrict__ A,
                                                    const float* __restrict__ B,
                                                    __half* __restrict__ C,
                                                    int n, int k, int m){
    extern __shared__ float smem[];
    float* As0 = smem;                          // 2 stages of [GBM][AS_STRIDE]
    float* Bs0 = smem + 2*GBM*AS_STRIDE;        // 2 stages of [GBK][BS_STRIDE]

    int tid  = threadIdx.x;
    int wid  = tid >> 5;
    int lane = tid & 31;
    int wm   = (wid & 3) * 32;
    int wn   = (wid >> 2) * 32;
    int grp  = lane >> 2;
    int tg   = lane & 3;

    int bm = blockIdx.y * GBM;
    int bn = blockIdx.x * GBN;

    float acc[2][4][4];
    #pragma unroll
    for (int i=0;i<2;i++)
        #pragma unroll
        for (int j=0;j<4;j++)
            #pragma unroll
            for (int l=0;l<4;l++) acc[i][j][l] = 0.f;

    auto load_stage = [&](int k0, int stage){
        float* As = As0 + stage*GBM*AS_STRIDE;
        float* Bs = Bs0 + stage*GBK*BS_STRIDE;
        #pragma unroll
        for (int i = 0; i < 4; i++){
            int ci  = tid + i*256;          // 0..1023
            int row = ci >> 3;              // 0..127
            int cc  = (ci & 7) * 4;         // float offset 0..28
            int gr  = bm + row;
            bool pred = gr < n;
            int grc = pred ? gr : (n - 1);  // keep address valid
            cp16(&As[row*AS_STRIDE + cc], &A[(size_t)grc * k + k0 + cc], pred);
        }
        #pragma unroll
        for (int i = 0; i < 2; i++){
            int ci  = tid + i*256;          // 0..511
            int row = ci >> 4;              // 0..31
            int cc  = (ci & 15) * 4;        // 0..60
            cp16(&Bs[row*BS_STRIDE + cc], &B[(size_t)(k0 + row) * m + bn + cc], true);
        }
        asm volatile("cp.async.commit_group;");
    };

    int iters = k / GBK;
    load_stage(0, 0);

    for (int it = 0; it < iters; it++){
        asm volatile("cp.async.wait_group 0;");
        __syncthreads();
        if (it + 1 < iters) load_stage((it + 1) * GBK, (it + 1) & 1);

        const float* As = As0 + (it & 1)*GBM*AS_STRIDE;
        const float* Bs = Bs0 + (it & 1)*GBK*BS_STRIDE;

        #pragma unroll
        for (int kk = 0; kk < 4; kk++){
            unsigned a[2][4], bfr[4][2];
            #pragma unroll
            for (int mt = 0; mt < 2; mt++){
                int r = wm + mt*16 + grp;
                int c = kk*8 + tg;
                a[mt][0] = __float_as_uint(As[ r     *AS_STRIDE + c    ]);
                a[mt][1] = __float_as_uint(As[(r + 8)*AS_STRIDE + c    ]);
                a[mt][2] = __float_as_uint(As[ r     *AS_STRIDE + c + 4]);
                a[mt][3] = __float_as_uint(As[(r + 8)*AS_STRIDE + c + 4]);
            }
            #pragma unroll
            for (int nt = 0; nt < 4; nt++){
                int c = wn + nt*8 + grp;
                int r = kk*8 + tg;
                bfr[nt][0] = __float_as_uint(Bs[ r     *BS_STRIDE + c]);
                bfr[nt][1] = __float_as_uint(Bs[(r + 4)*BS_STRIDE + c]);
            }
            #pragma unroll
            for (int mt = 0; mt < 2; mt++)
                #pragma unroll
                for (int nt = 0; nt < 4; nt++){
                    asm volatile(
                        "mma.sync.aligned.m16n8k8.row.col.f32.tf32.tf32.f32 "
                        "{%0,%1,%2,%3}, {%4,%5,%6,%7}, {%8,%9}, {%0,%1,%2,%3};"
                        : "+f"(acc[mt][nt][0]), "+f"(acc[mt][nt][1]),
                          "+f"(acc[mt][nt][2]), "+f"(acc[mt][nt][3])
                        : "r"(a[mt][0]), "r"(a[mt][1]), "r"(a[mt][2]), "r"(a[mt][3]),
                          "r"(bfr[nt][0]), "r"(bfr[nt][1]));
                }
        }
        __syncthreads();
    }

    #pragma unroll
    for (int mt = 0; mt < 2; mt++){
        int r0 = bm + wm + mt*16 + grp;
        int r1 = r0 + 8;
        #pragma unroll
        for (int nt = 0; nt < 4; nt++){
            int c = bn + wn + nt*8 + 2*tg;
            if (r0 < n) *(__half2*)&C[(size_t)r0 * m + c] = __floats2half2_rn(acc[mt][nt][0], acc[mt][nt][1]);
            if (r1 < n) *(__half2*)&C[(size_t)r1 * m + c] = __floats2half2_rn(acc[mt][nt][2], acc[mt][nt][3]);
        }
    }
}

// ------- attention logits H=4: ONE warp per node; 2x uint4 per lane = full 512 halves -------
__global__ void attn_logits4(const __half* __restrict__ xh, const float* __restrict__ as_,
                             const float* __restrict__ ad_, float* __restrict__ als,
                             float* __restrict__ ald){
    int node = (blockIdx.x * blockDim.x + threadIdx.x) >> 5;
    if (node >= Nn) return;
    int lane = threadIdx.x & 31;
    int hd = lane >> 3;
    int sl = lane & 7;

    const uint4* xr = (const uint4*)(xh + (size_t)node * F1) + hd*16 + sl*2;
    uint4 u0 = xr[0], u1 = xr[1];
    float4 x0 = h4_to_f4(u0.x, u0.y);
    float4 x1 = h4_to_f4(u0.z, u0.w);
    float4 x2 = h4_to_f4(u1.x, u1.y);
    float4 x3 = h4_to_f4(u1.z, u1.w);
    const float4* svp = (const float4*)(as_ + hd * HIDC) + sl*4;
    const float4* dvp = (const float4*)(ad_ + hd * HIDC) + sl*4;
    float4 s0 = svp[0], s1 = svp[1], s2 = svp[2], s3 = svp[3];
    float4 d0 = dvp[0], d1 = dvp[1], d2 = dvp[2], d3 = dvp[3];
    float s = x0.x*s0.x + x0.y*s0.y + x0.z*s0.z + x0.w*s0.w
            + x1.x*s1.x + x1.y*s1.y + x1.z*s1.z + x1.w*s1.w
            + x2.x*s2.x + x2.y*s2.y + x2.z*s2.z + x2.w*s2.w
            + x3.x*s3.x + x3.y*s3.y + x3.z*s3.z + x3.w*s3.w;
    float d = x0.x*d0.x + x0.y*d0.y + x0.z*d0.z + x0.w*d0.w
            + x1.x*d1.x + x1.y*d1.y + x1.z*d1.z + x1.w*d1.w
            + x2.x*d2.x + x2.y*d2.y + x2.z*d2.z + x2.w*d2.w
            + x3.x*d3.x + x3.y*d3.y + x3.z*d3.z + x3.w*d3.w;
    #pragma unroll
    for (int o = 4; o; o >>= 1){
        s += __shfl_xor_sync(0xffffffffu, s, o);
        d += __shfl_xor_sync(0xffffffffu, d, o);
    }
    if (sl == 0){ als[node*NH1 + hd] = s; ald[node*NH1 + hd] = d; }
}

// ------- attention logits H=1 (fp16 features) -------
__global__ void attn_logits1(const __half* __restrict__ xh, const float* __restrict__ as_,
                             const float* __restrict__ ad_, float* __restrict__ als,
                             float* __restrict__ ald){
    int w = (blockIdx.x * blockDim.x + threadIdx.x) >> 5;
    if (w >= Nn) return;
    int lane = threadIdx.x & 31;
    uint2 u = ((const uint2*)(xh + (size_t)w * HIDC))[lane];
    float4 x = h4_to_f4(u.x, u.y);
    float4 sv = ((const float4*)as_)[lane];
    float4 dv = ((const float4*)ad_)[lane];
    float s = x.x*sv.x + x.y*sv.y + x.z*sv.z + x.w*sv.w;
    float d = x.x*dv.x + x.y*dv.y + x.z*dv.z + x.w*dv.w;
    s = wsum(s); d = wsum(d);
    if (lane == 0){ als[w] = s; ald[w] = d; }
}

// ------ GAT agg H=4: two warps/node; SINGLE PASS (no max shift — logits << 88) ------
__global__ void __launch_bounds__(256) gat_agg4_fused(const float4* __restrict__ als4,
                                                      const float4* __restrict__ ald4,
                                                      const __half* __restrict__ xh,
                                                      const float* __restrict__ bias,
                                                      const float* __restrict__ gw,
                                                      const float* __restrict__ bw,
                                                      float* __restrict__ h1){
    __shared__ float s_part[8], q_part[8];
    int wib  = threadIdx.x >> 5;
    int node = blockIdx.x * 4 + (wib >> 1);
    int sub  = wib & 1;
    int lane = threadIdx.x & 31;
    int hsel = lane >> 4;

    float4 adv = ald4[node];
    float ad0 = sub ? adv.z : adv.x;
    float ad1 = sub ? adv.w : adv.y;
    int pbeg = g_rowptr[node], pend = g_rowptr[node+1];

    float den0 = 0.f, den1 = 0.f;
    float4 aA = make_float4(0,0,0,0), aB = aA;
    #pragma unroll 4
    for (int p = pbeg; p < pend; p++){
        int s = g_csr_src[p];
        float4 as = als4[s];
        float e0 = __expf(lrelu((sub ? as.z : as.x) + ad0));
        float e1 = __expf(lrelu((sub ? as.w : as.y) + ad1));
        den0 += e0; den1 += e1;
        float e = hsel ? e1 : e0;
        uint4 u = ((const uint4*)(xh + (size_t)s * F1 + sub*256))[lane];
        float4 xA = h4_to_f4(u.x, u.y);
        float4 xB = h4_to_f4(u.z, u.w);
        aA.x += e*xA.x; aA.y += e*xA.y; aA.z += e*xA.z; aA.w += e*xA.w;
        aB.x += e*xB.x; aB.y += e*xB.y; aB.z += e*xB.z; aB.w += e*xB.w;
    }
    float rh = 1.f / (hsel ? den1 : den0);

    const float4* b4 = (const float4*)bias + sub*64 + lane*2;
    float4 qA = b4[0], qB = b4[1];
    float4 vA, vB;
    vA.x = aA.x*rh + qA.x; vA.y = aA.y*rh + qA.y; vA.z = aA.z*rh + qA.z; vA.w = aA.w*rh + qA.w;
    vB.x = aB.x*rh + qB.x; vB.y = aB.y*rh + qB.y; vB.z = aB.z*rh + qB.z; vB.w = aB.w*rh + qB.w;

    float ssum = wsum(vA.x+vA.y+vA.z+vA.w + vB.x+vB.y+vB.z+vB.w);
    if (lane == 0) s_part[wib] = ssum;
    __syncthreads();
    int base = wib & ~1;
    float mu = (s_part[base] + s_part[base+1]) * (1.0f / F1);

    float q = 0.f, dx;
    dx=vA.x-mu; q+=dx*dx; dx=vA.y-mu; q+=dx*dx; dx=vA.z-mu; q+=dx*dx; dx=vA.w-mu; q+=dx*dx;
    dx=vB.x-mu; q+=dx*dx; dx=vB.y-mu; q+=dx*dx; dx=vB.z-mu; q+=dx*dx; dx=vB.w-mu; q+=dx*dx;
    q = wsum(q);
    if (lane == 0) q_part[wib] = q;
    __syncthreads();
    float rstd = rsqrtf((q_part[base] + q_part[base+1]) * (1.0f / F1) + 1e-5f);

    const float4* g4 = (const float4*)gw + sub*64 + lane*2;
    const float4* w4 = (const float4*)bw + sub*64 + lane*2;
    float4* orow = (float4*)(h1 + (size_t)node * F1) + sub*64 + lane*2;
    float4 gg = g4[0], bb = w4[0];
    float4 y;
    y.x = gelu_exact((vA.x - mu) * rstd * gg.x + bb.x);
    y.y = gelu_exact((vA.y - mu) * rstd * gg.y + bb.y);
    y.z = gelu_exact((vA.z - mu) * rstd * gg.z + bb.z);
    y.w = gelu_exact((vA.w - mu) * rstd * gg.w + bb.w);
    orow[0] = y;
    gg = g4[1]; bb = w4[1];
    y.x = gelu_exact((vB.x - mu) * rstd * gg.x + bb.x);
    y.y = gelu_exact((vB.y - mu) * rstd * gg.y + bb.y);
    y.z = gelu_exact((vB.z - mu) * rstd * gg.z + bb.z);
    y.w = gelu_exact((vB.w - mu) * rstd * gg.w + bb.w);
    orow[1] = y;
}

// ------- GAT agg H=1: SINGLE PASS + bias+LN+GELU+out_proj+log_softmax -------
__global__ void __launch_bounds__(256) gat_agg1_fused(const float* __restrict__ als,
                                                      const float* __restrict__ ald,
                                                      const __half* __restrict__ xh,
                                                      const float* __restrict__ bias,
                                                      const float* __restrict__ gw,
                                                      const float* __restrict__ bw,
                                                      const float* __restrict__ Wo,
                                                      const float* __restrict__ bo,
                                                      float* __restrict__ out){
    int node = blockIdx.x * (blockDim.x >> 5) + (threadIdx.x >> 5);
    if (node >= Nn) return;
    int lane = threadIdx.x & 31;
    float ad = ald[node];
    int pbeg = g_rowptr[node], pend = g_rowptr[node+1];

    float den = 0.f;
    float4 acc = make_float4(0,0,0,0);
    #pragma unroll 4
    for (int p = pbeg; p < pend; p++){
        int s = g_csr_src[p];
        float e = __expf(lrelu(als[s] + ad));
        den += e;
        uint2 u = ((const uint2*)(xh + (size_t)s * HIDC))[lane];
        float4 xv = h4_to_f4(u.x, u.y);
        acc.x += e*xv.x; acc.y += e*xv.y; acc.z += e*xv.z; acc.w += e*xv.w;
    }
    float r = 1.f/den;

    float4 qb = ((const float4*)bias)[lane];
    float4 v;
    v.x = acc.x*r + qb.x; v.y = acc.y*r + qb.y; v.z = acc.z*r + qb.z; v.w = acc.w*r + qb.w;
    float s = wsum(v.x + v.y + v.z + v.w);
    float mu = s * (1.0f / HIDC);
    float q = 0.f, dx;
    dx=v.x-mu; q+=dx*dx; dx=v.y-mu; q+=dx*dx; dx=v.z-mu; q+=dx*dx; dx=v.w-mu; q+=dx*dx;
    q = wsum(q);
    float rstd = rsqrtf(q * (1.0f / HIDC) + 1e-5f);
    float4 gg = ((const float4*)gw)[lane];
    float4 bb = ((const float4*)bw)[lane];
    float4 y;
    y.x = gelu_exact((v.x - mu) * rstd * gg.x + bb.x);
    y.y = gelu_exact((v.y - mu) * rstd * gg.y + bb.y);
    y.z = gelu_exact((v.z - mu) * rstd * gg.z + bb.z);
    y.w = gelu_exact((v.w - mu) * rstd * gg.w + bb.w);

    float z = bo[lane];
    #pragma unroll 8
    for (int k4 = 0; k4 < 32; k4++){
        float yx = __shfl_sync(0xffffffffu, y.x, k4);
        float yy = __shfl_sync(0xffffffffu, y.y, k4);
        float yz = __shfl_sync(0xffffffffu, y.z, k4);
        float yw = __shfl_sync(0xffffffffu, y.w, k4);
        const float* wr = Wo + k4*4*DOUT + lane;
        z += yx*wr[0] + yy*wr[DOUT] + yz*wr[2*DOUT] + yw*wr[3*DOUT];
    }
    float mx = wmax(z);
    float ex = expf(z - mx);
    float sm = wsum(ex);
    out[(size_t)node * DOUT + lane] = z - mx - logf(sm);
}

// ---------------- launch ----------------
extern "C" void kernel_launch(void* const* d_in, const int* in_sizes, int n_in,
                              void* d_out, int out_size){
    const float* x      = (const float*)d_in[0];
    const void*  ei     = d_in[1];
    const float* g_in   = (const float*)d_in[2];
    const float* b_in   = (const float*)d_in[3];
    const float* W1     = (const float*)d_in[4];
    const float* att1_s = (const float*)d_in[5];
    const float* att1_d = (const float*)d_in[6];
    const float* bias1  = (const float*)d_in[7];
    const float* g1     = (const float*)d_in[8];
    const float* b1     = (const float*)d_in[9];
    const float* W2     = (const float*)d_in[10];
    const float* att2_s = (const float*)d_in[11];
    const float* att2_d = (const float*)d_in[12];
    const float* bias2  = (const float*)d_in[13];
    const float* g2     = (const float*)d_in[14];
    const float* b2     = (const float*)d_in[15];
    const float* Wo     = (const float*)d_in[16];
    const float* bo     = (const float*)d_in[17];
    float* out = (float*)d_out;

    void *p_h0, *p_xh1, *p_al1s, *p_al1d, *p_h1;
    void *p_xh2, *p_al2s, *p_al2d, *p_is32, *p_deg;
    cudaGetSymbolAddress(&p_h0,   g_h0);
    cudaGetSymbolAddress(&p_xh1,  g_xh1);
    cudaGetSymbolAddress(&p_al1s, g_al1s);
    cudaGetSymbolAddress(&p_al1d, g_al1d);
    cudaGetSymbolAddress(&p_h1,   g_h1);
    cudaGetSymbolAddress(&p_xh2,  g_xh2);
    cudaGetSymbolAddress(&p_al2s, g_al2s);
    cudaGetSymbolAddress(&p_al2d, g_al2d);
    cudaGetSymbolAddress(&p_is32, g_is32);
    cudaGetSymbolAddress(&p_deg,  g_deg);

    static int smem_set = 0;
    if (!smem_set){
        cudaFuncSetAttribute(gemm_tf32, cudaFuncAttributeMaxDynamicSharedMemorySize, GEMM_SMEM);
        smem_set = 1;
    }

    const int T = 256;
    const int warpsPB = T / 32;

    // ---- side stream for CSR build (fork/join via events; capture-legal) ----
    cudaStream_t s2;
    cudaStreamCreate(&s2);
    cudaEvent_t evF, evJ;
    cudaEventCreateWithFlags(&evF, cudaEventDisableTiming);
    cudaEventCreateWithFlags(&evJ, cudaEventDisableTiming);

    cudaEventRecord(evF, 0);
    cudaStreamWaitEvent(s2, evF, 0);

    cudaMemsetAsync(p_is32, 0, sizeof(int), s2);
    cudaMemsetAsync(p_deg,  0, Nn * sizeof(int), s2);
    detect_dtype<<<16, 256, 0, s2>>>((const long long*)ei);
    decode_edges<<<(ETOT + T - 1)/T, T, 0, s2>>>((const int*)ei);
    scan_tiles<<<NTILES, 256, 0, s2>>>();
    scan_sums<<<1, 128, 0, s2>>>();
    scan_finalize<<<NTILES, 256, 0, s2>>>();
    build_csr<<<(ETOT + T - 1)/T, T, 0, s2>>>();
    cudaEventRecord(evJ, s2);

    // ---- dense path on main stream ----
    ln_kernel<128><<<(Nn + warpsPB - 1)/warpsPB, T>>>(x, g_in, b_in, (float*)p_h0);
    {
        dim3 grid(F1/GBN, (Nn + GBM - 1)/GBM);
        gemm_tf32<<<grid, 256, GEMM_SMEM>>>((const float*)p_h0, W1, (__half*)p_xh1, Nn, DIN, F1);
    }
    attn_logits4<<<(Nn + warpsPB - 1)/warpsPB, T>>>((const __half*)p_xh1, att1_s, att1_d,
                                                    (float*)p_al1s, (float*)p_al1d);

    // join CSR before aggregation
    cudaStreamWaitEvent(0, evJ, 0);

    gat_agg4_fused<<<Nn/4, T>>>((const float4*)p_al1s, (const float4*)p_al1d,
                                (const __half*)p_xh1, bias1, g1, b1, (float*)p_h1);

    {
        dim3 grid(HIDC/GBN, (Nn + GBM - 1)/GBM);
        gemm_tf32<<<grid, 256, GEMM_SMEM>>>((const float*)p_h1, W2, (__half*)p_xh2, Nn, F1, HIDC);
    }
    attn_logits1<<<(Nn + warpsPB - 1)/warpsPB, T>>>((const __half*)p_xh2, att2_s, att2_d,
                                                    (float*)p_al2s, (float*)p_al2d);
    gat_agg1_fused<<<(Nn + warpsPB - 1)/warpsPB, T>>>((const float*)p_al2s, (const float*)p_al2d,
                                                      (const __half*)p_xh2, bias2, g2, b2,
                                                      Wo, bo, out);
}